// round 2
// baseline (speedup 1.0000x reference)
#include <cuda_runtime.h>

#define N_NODES 524288
#define NB      4096
#define BS      128
#define MAXKV   64

// Per-block scratch (no allocations allowed; __device__ globals are the sanctioned path).
// Fully overwritten every launch -> no reset needed across graph replays.
__device__ float g_psum[NB];   // sum over block of p*keep
__device__ float g_kcnt[NB];   // sum over block of keep
__device__ float g_bce[NB];    // sum over block of bce*sup
__device__ float g_sup[NB];    // sum over block of sup
__device__ float g_gl[NB];     // blk_loss * valid
__device__ float g_val[NB];    // valid flag

__device__ __forceinline__ float warp_sum(float v) {
#pragma unroll
    for (int o = 16; o > 0; o >>= 1) v += __shfl_down_sync(0xffffffffu, v, o);
    return v;
}

// Masks arrive as 4-byte elements (bool promoted to int32 0/1 or float32 0.0/1.0).
// Nonzero bit-pattern == true under BOTH encodings (1 and 0x3F800000).
__device__ __forceinline__ bool mask_true(const unsigned int* m, int idx) {
    return m[idx] != 0u;
}

// Kernel A: per-node math + per-block reductions of 4 scalars.
__global__ void __launch_bounds__(BS) kernA(const float* __restrict__ x,
                                            const float* __restrict__ t,
                                            const unsigned int* __restrict__ sup,
                                            const unsigned int* __restrict__ ign) {
    const int b   = blockIdx.x;
    const int tid = threadIdx.x;
    const int idx = b * BS + tid;

    const float xv = x[idx];
    const float tv = t[idx];
    const bool  s    = mask_true(sup, idx);
    const bool  keep = !mask_true(ign, idx);

    // stable softplus: max(x,0) + log1p(exp(-|x|))
    const float sp  = fmaxf(xv, 0.0f) + log1pf(__expf(-fabsf(xv)));
    const float bce = sp - tv * xv;
    const float p   = 1.0f / (1.0f + __expf(-xv));

    float v0 = s    ? bce  : 0.0f;
    float v1 = s    ? 1.0f : 0.0f;
    float v2 = keep ? p    : 0.0f;
    float v3 = keep ? 1.0f : 0.0f;

    __shared__ float sh[4][4];
    v0 = warp_sum(v0); v1 = warp_sum(v1); v2 = warp_sum(v2); v3 = warp_sum(v3);
    const int lane = tid & 31, w = tid >> 5;
    if (lane == 0) { sh[0][w] = v0; sh[1][w] = v1; sh[2][w] = v2; sh[3][w] = v3; }
    __syncthreads();
    if (tid == 0) {
        float a = 0.f, bb = 0.f, c = 0.f, d = 0.f;
#pragma unroll
        for (int i = 0; i < 4; i++) { a += sh[0][i]; bb += sh[1][i]; c += sh[2][i]; d += sh[3][i]; }
        g_bce[b]  = a;
        g_sup[b]  = bb;
        g_psum[b] = c;
        g_kcnt[b] = d;
    }
}

// Kernel B: neighbor scalar gather -> n_mean; then per-block graph loss.
__global__ void __launch_bounds__(BS) kernB(const float* __restrict__ x,
                                            const unsigned int* __restrict__ sup,
                                            const unsigned int* __restrict__ ign,
                                            const int* __restrict__ kvi,
                                            const int* __restrict__ kvn) {
    const int b   = blockIdx.x;
    const int tid = threadIdx.x;
    const int lane = tid & 31, w = tid >> 5;

    __shared__ float sh[2][4];
    __shared__ float sh_nmean, sh_ncnt;

    const int nb = kvn[b];
    float ns = 0.0f, nc = 0.0f;
    if (tid < MAXKV && tid < nb) {
        const int j = kvi[b * MAXKV + tid];
        ns = g_psum[j];
        nc = g_kcnt[j];
    }
    ns = warp_sum(ns); nc = warp_sum(nc);
    if (lane == 0) { sh[0][w] = ns; sh[1][w] = nc; }
    __syncthreads();
    if (tid == 0) {
        const float a = sh[0][0] + sh[0][1] + sh[0][2] + sh[0][3];
        const float c = sh[1][0] + sh[1][1] + sh[1][2] + sh[1][3];
        sh_ncnt  = c;
        sh_nmean = a / fmaxf(c, 1.0f);
    }
    __syncthreads();
    const float n_mean = sh_nmean;
    const float n_cnt  = sh_ncnt;

    const int idx = b * BS + tid;
    const float xv = x[idx];
    const float p  = 1.0f / (1.0f + __expf(-xv));
    const bool unc = !mask_true(ign, idx) && !mask_true(sup, idx);
    const float d  = p - n_mean;
    float sq = unc ? d * d : 0.0f;
    float q  = unc ? 1.0f : 0.0f;

    sq = warp_sum(sq); q = warp_sum(q);
    __syncthreads();  // protect sh reuse
    if (lane == 0) { sh[0][w] = sq; sh[1][w] = q; }
    __syncthreads();
    if (tid == 0) {
        const float sqs = sh[0][0] + sh[0][1] + sh[0][2] + sh[0][3];
        const float qc  = sh[1][0] + sh[1][1] + sh[1][2] + sh[1][3];
        const bool valid = (qc > 0.0f) && (n_cnt > 0.0f);
        g_gl[b]  = valid ? (sqs / fmaxf(qc, 1.0f)) : 0.0f;
        g_val[b] = valid ? 1.0f : 0.0f;
    }
}

// Kernel C: final reduction of the length-NB arrays -> scalar loss.
__global__ void __launch_bounds__(256) kernC(float* __restrict__ out) {
    const int tid = threadIdx.x;
    float a = 0.f, b = 0.f, c = 0.f, d = 0.f;
    for (int i = tid; i < NB; i += 256) {
        a += g_bce[i];
        b += g_sup[i];
        c += g_gl[i];
        d += g_val[i];
    }
    __shared__ float sh[4][8];
    a = warp_sum(a); b = warp_sum(b); c = warp_sum(c); d = warp_sum(d);
    const int lane = tid & 31, w = tid >> 5;
    if (lane == 0) { sh[0][w] = a; sh[1][w] = b; sh[2][w] = c; sh[3][w] = d; }
    __syncthreads();
    if (tid == 0) {
        float A = 0.f, B = 0.f, C = 0.f, D = 0.f;
#pragma unroll
        for (int i = 0; i < 8; i++) { A += sh[0][i]; B += sh[1][i]; C += sh[2][i]; D += sh[3][i]; }
        const float loss_sup   = (B > 0.0f) ? (A / fmaxf(B, 1.0f)) : 0.0f;
        const float loss_graph = C / fmaxf(D, 1.0f);
        out[0] = loss_sup + 0.3f * loss_graph;
    }
}

extern "C" void kernel_launch(void* const* d_in, const int* in_sizes, int n_in,
                              void* d_out, int out_size) {
    const float*        x   = (const float*)d_in[0];         // logits   [524288]
    const float*        t   = (const float*)d_in[1];         // targets  [524288]
    const unsigned int* sup = (const unsigned int*)d_in[2];  // sup_mask (bool -> 4-byte 0/1 or 0.0/1.0)
    const unsigned int* ign = (const unsigned int*)d_in[3];  // ignore_mask
    const int*          kvi = (const int*)d_in[4];           // kv_indices [4096*64]
    const int*          kvn = (const int*)d_in[5];           // kv_num_blocks [4096]
    (void)in_sizes; (void)n_in; (void)out_size;

    kernA<<<NB, BS>>>(x, t, sup, ign);
    kernB<<<NB, BS>>>(x, sup, ign, kvi, kvn);
    kernC<<<1, 256>>>((float*)d_out);
}

// round 3
// speedup vs baseline: 1.6072x; 1.6072x over previous
#include <cuda_runtime.h>

#define N_NODES 524288
#define NB      4096
#define BS      128
#define MAXKV   64
#define CTA     256   // 8 warps; one warp per logical block

// Per-block scratch. Fully overwritten every launch -> graph-replay safe.
__device__ float g_psum[NB];   // sum over block of p*keep
__device__ float g_kcnt[NB];   // sum over block of keep
__device__ float g_bce[NB];    // sum over block of bce*sup
__device__ float g_sup[NB];    // sum over block of sup
__device__ float g_gl[NB];     // blk_loss * valid
__device__ float g_val[NB];    // valid flag

__device__ __forceinline__ float warp_sum(float v) {
#pragma unroll
    for (int o = 16; o > 0; o >>= 1) v += __shfl_down_sync(0xffffffffu, v, o);
    return v;
}

// One exp serves both softplus and sigmoid.
__device__ __forceinline__ void node_math(float x, float& sp, float& p) {
    const float e = __expf(-fabsf(x));
    sp = fmaxf(x, 0.0f) + __logf(1.0f + e);
    const float inv = 1.0f / (1.0f + e);
    p = (x >= 0.0f) ? inv : e * inv;
}

// Kernel A: warp per logical block; float4/uint4 loads; 4 per-block scalars.
__global__ void __launch_bounds__(CTA) kernA(const float4* __restrict__ x4,
                                             const float4* __restrict__ t4,
                                             const uint4*  __restrict__ s4,
                                             const uint4*  __restrict__ i4) {
    const int gw   = (blockIdx.x * CTA + threadIdx.x) >> 5;  // global warp == logical block b
    const int lane = threadIdx.x & 31;
    const int vidx = gw * 32 + lane;   // 32 float4 per 128-node block

    const float4 xv = x4[vidx];
    const float4 tv = t4[vidx];
    const uint4  sv = s4[vidx];
    const uint4  iv = i4[vidx];

    float v0 = 0.f, v1 = 0.f, v2 = 0.f, v3 = 0.f;
    {
        const float xs[4] = {xv.x, xv.y, xv.z, xv.w};
        const float ts[4] = {tv.x, tv.y, tv.z, tv.w};
        const unsigned int ss[4] = {sv.x, sv.y, sv.z, sv.w};
        const unsigned int is[4] = {iv.x, iv.y, iv.z, iv.w};
#pragma unroll
        for (int k = 0; k < 4; k++) {
            float sp, p;
            node_math(xs[k], sp, p);
            const float bce = sp - ts[k] * xs[k];
            const bool s    = ss[k] != 0u;
            const bool keep = is[k] == 0u;
            if (s)    { v0 += bce; v1 += 1.0f; }
            if (keep) { v2 += p;   v3 += 1.0f; }
        }
    }
    v0 = warp_sum(v0); v1 = warp_sum(v1); v2 = warp_sum(v2); v3 = warp_sum(v3);
    if (lane == 0) {
        g_bce[gw]  = v0;
        g_sup[gw]  = v1;
        g_psum[gw] = v2;
        g_kcnt[gw] = v3;
    }
}

// Kernel B: warp per logical block; neighbor scalar gather -> n_mean; graph loss.
__global__ void __launch_bounds__(CTA) kernB(const float4* __restrict__ x4,
                                             const uint4*  __restrict__ s4,
                                             const uint4*  __restrict__ i4,
                                             const int*    __restrict__ kvi,
                                             const int*    __restrict__ kvn) {
    const int b    = (blockIdx.x * CTA + threadIdx.x) >> 5;
    const int lane = threadIdx.x & 31;

    // Phase 1: gather up to 64 neighbor block scalars (2 per lane).
    const int nb = kvn[b];
    const int j0 = kvi[b * MAXKV + lane];
    const int j1 = kvi[b * MAXKV + 32 + lane];
    float ns = 0.0f, nc = 0.0f;
    if (lane < nb)      { ns += g_psum[j0]; nc += g_kcnt[j0]; }
    if (lane + 32 < nb) { ns += g_psum[j1]; nc += g_kcnt[j1]; }
    ns = warp_sum(ns); nc = warp_sum(nc);
    ns = __shfl_sync(0xffffffffu, ns, 0);
    nc = __shfl_sync(0xffffffffu, nc, 0);
    const float n_mean = ns / fmaxf(nc, 1.0f);

    // Phase 2: per-node squared deviation over uncertain nodes.
    const int vidx = b * 32 + lane;
    const float4 xv = x4[vidx];
    const uint4  sv = s4[vidx];
    const uint4  iv = i4[vidx];

    float sq = 0.f, q = 0.f;
    {
        const float xs[4] = {xv.x, xv.y, xv.z, xv.w};
        const unsigned int ss[4] = {sv.x, sv.y, sv.z, sv.w};
        const unsigned int is[4] = {iv.x, iv.y, iv.z, iv.w};
#pragma unroll
        for (int k = 0; k < 4; k++) {
            const float e = __expf(-fabsf(xs[k]));
            const float inv = 1.0f / (1.0f + e);
            const float p = (xs[k] >= 0.0f) ? inv : e * inv;
            if (is[k] == 0u && ss[k] == 0u) {
                const float d = p - n_mean;
                sq += d * d;
                q  += 1.0f;
            }
        }
    }
    sq = warp_sum(sq); q = warp_sum(q);
    if (lane == 0) {
        const bool valid = (q > 0.0f) && (nc > 0.0f);
        g_gl[b]  = valid ? (sq / fmaxf(q, 1.0f)) : 0.0f;
        g_val[b] = valid ? 1.0f : 0.0f;
    }
}

// Kernel C: final reduction of the length-NB arrays -> scalar loss.
__global__ void __launch_bounds__(256) kernC(float* __restrict__ out) {
    const int tid = threadIdx.x;
    float a = 0.f, b = 0.f, c = 0.f, d = 0.f;
    for (int i = tid; i < NB; i += 256) {
        a += g_bce[i];
        b += g_sup[i];
        c += g_gl[i];
        d += g_val[i];
    }
    __shared__ float sh[4][8];
    a = warp_sum(a); b = warp_sum(b); c = warp_sum(c); d = warp_sum(d);
    const int lane = tid & 31, w = tid >> 5;
    if (lane == 0) { sh[0][w] = a; sh[1][w] = b; sh[2][w] = c; sh[3][w] = d; }
    __syncthreads();
    if (tid == 0) {
        float A = 0.f, B = 0.f, C = 0.f, D = 0.f;
#pragma unroll
        for (int i = 0; i < 8; i++) { A += sh[0][i]; B += sh[1][i]; C += sh[2][i]; D += sh[3][i]; }
        const float loss_sup   = (B > 0.0f) ? (A / fmaxf(B, 1.0f)) : 0.0f;
        const float loss_graph = C / fmaxf(D, 1.0f);
        out[0] = loss_sup + 0.3f * loss_graph;
    }
}

extern "C" void kernel_launch(void* const* d_in, const int* in_sizes, int n_in,
                              void* d_out, int out_size) {
    const float4* x4 = (const float4*)d_in[0];  // logits   [524288] f32
    const float4* t4 = (const float4*)d_in[1];  // targets  [524288] f32
    const uint4*  s4 = (const uint4*)d_in[2];   // sup_mask  (4-byte bool)
    const uint4*  i4 = (const uint4*)d_in[3];   // ignore_mask
    const int*   kvi = (const int*)d_in[4];     // kv_indices [4096*64]
    const int*   kvn = (const int*)d_in[5];     // kv_num_blocks [4096]
    (void)in_sizes; (void)n_in; (void)out_size;

    kernA<<<NB / (CTA / 32), CTA>>>(x4, t4, s4, i4);
    kernB<<<NB / (CTA / 32), CTA>>>(x4, s4, i4, kvi, kvn);
    kernC<<<1, 256>>>((float*)d_out);
}